// round 10
// baseline (speedup 1.0000x reference)
#include <cuda_runtime.h>

#define CUT2 25.0f
#define IT 4            // i-rows per group (register tile)
#define NROWS_CAP 65536
#define NGRP_CAP  (NROWS_CAP / IT)
#define MAXCH64 16      // max 64-wide j-chunks per row (nat <= 1024)
#define NSYS_CAP 2048
#define NSYS_SM 257

// Scratch (static __device__, allocation-free).
// Mask words per (group, chunk64): [e0,o0,e1,o1,e2,o2,e3,o3] where e/o are
// ballots over even/odd j within the 64-j chunk, rows 0..3 of the group.
__device__ unsigned g_maskw[(size_t)NGRP_CAP * MAXCH64 * 8];   // 8 MB
__device__ int4  g_counts4[NGRP_CAP];       // per-group 4-row hit counts
__device__ int   g_offsets[NROWS_CAP];      // within-system exclusive prefix
__device__ int   g_systot[NSYS_CAP];        // per-system totals

// ---- bit-exact reference arithmetic (DO NOT CHANGE) ----
__device__ __forceinline__ float sqnorm3(float x, float y, float z) {
    return __fadd_rn(__fadd_rn(__fmul_rn(x, x), __fmul_rn(y, y)), __fmul_rn(z, z));
}
// gram dot via GEMM-style FMA chain: c = rn(x*x'); c = fma(y,y',c); c = fma(z,z',c)
__device__ __forceinline__ float dot3(float4 a, float4 b) {
    return __fmaf_rn(a.z, b.z, __fmaf_rn(a.y, b.y, __fmul_rn(a.x, b.x)));
}
__device__ __forceinline__ float d12_of(float4 ai, float4 aj) {
    return __fsub_rn(__fadd_rn(ai.w, aj.w), __fmul_rn(2.0f, dot3(ai, aj)));
}
// --------------------------------------------------------

// ---- packed f32x2 helpers ----
typedef unsigned long long u64;
__device__ __forceinline__ u64 pack2(float lo, float hi) {
    u64 r; asm("mov.b64 %0, {%1, %2};" : "=l"(r) : "f"(lo), "f"(hi)); return r;
}
__device__ __forceinline__ void unpack2(u64 v, float& lo, float& hi) {
    asm("mov.b64 {%0, %1}, %2;" : "=f"(lo), "=f"(hi) : "l"(v));
}
__device__ __forceinline__ u64 mul2p(u64 a, u64 b) {
    u64 r; asm("mul.rn.f32x2 %0, %1, %2;" : "=l"(r) : "l"(a), "l"(b)); return r;
}
__device__ __forceinline__ u64 add2p(u64 a, u64 b) {
    u64 r; asm("add.rn.f32x2 %0, %1, %2;" : "=l"(r) : "l"(a), "l"(b)); return r;
}
__device__ __forceinline__ u64 fma2p(u64 a, u64 b, u64 c) {
    u64 r; asm("fma.rn.f32x2 %0, %1, %2, %3;" : "=l"(r) : "l"(a), "l"(b), "l"(c));
    return r;
}
// Packed d12 for one row vs a j-PAIR. Row regs hold (-x_i, -x_i) etc (exact
// negation); j regs hold (2x_j0, 2x_j1) etc. Chain computes -2*dot exactly
// per half (rn(-u) = -rn(u), rn(2u) = 2 rn(u)); final add2 = rn(w - 2*dot):
// bit-identical to the reference d12 for both j's.
__device__ __forceinline__ u64 d12_jpair(u64 nax, u64 nay, u64 naz, u64 aw,
                                         u64 jx, u64 jy, u64 jz, u64 jw) {
    u64 t = mul2p(nax, jx);
    t = fma2p(nay, jy, t);
    t = fma2p(naz, jz, t);
    return add2p(add2p(aw, jw), t);
}
// Bit-expand u32 -> even bits of u64 (morton half-interleave).
__device__ __forceinline__ u64 bexpand(unsigned v) {
    u64 x = v;
    x = (x | (x << 16)) & 0x0000FFFF0000FFFFull;
    x = (x | (x << 8))  & 0x00FF00FF00FF00FFull;
    x = (x | (x << 4))  & 0x0F0F0F0F0F0F0F0Full;
    x = (x | (x << 2))  & 0x3333333333333333ull;
    x = (x | (x << 1))  & 0x5555555555555555ull;
    return x;
}
// --------------------------------------------------------

extern __shared__ ulonglong2 s_pk2[];

// K1: j-paired mask sweep. smem holds, per j-pair p = (2p, 2p+1):
//   s_xy[p] = { (2x_j0,2x_j1), (2y_j0,2y_j1) }
//   s_zw[p] = { (2z_j0,2z_j1), (sq_j0,sq_j1) }
// Warp handles IT=4 consecutive rows; per 64-j chunk: 2 LDS.128 + packed math
// for 4 rows, 8 ballots (even/odd j), counts accumulated, 2 STG.128 of masks.
__global__ void sweep_kernel(const float* __restrict__ coords, int nat,
                             int nch64, int ngroups) {
    int npr = nch64 * 32;                 // j-pairs incl. sentinel tail
    ulonglong2* s_xy = s_pk2;
    ulonglong2* s_zw = s_pk2 + npr;
    int s = blockIdx.x;
    {
        const float* base = coords + (size_t)s * nat * 3;
        for (int p = threadIdx.x; p < npr; p += blockDim.x) {
            int j0 = 2 * p, j1 = 2 * p + 1;
            float x0 = 0.f, y0 = 0.f, z0 = 0.f, w0 = 1e30f;
            float x1 = 0.f, y1 = 0.f, z1 = 0.f, w1 = 1e30f;
            if (j0 < nat) {
                x0 = base[3 * j0]; y0 = base[3 * j0 + 1]; z0 = base[3 * j0 + 2];
                w0 = sqnorm3(x0, y0, z0);
            }
            if (j1 < nat) {
                x1 = base[3 * j1]; y1 = base[3 * j1 + 1]; z1 = base[3 * j1 + 2];
                w1 = sqnorm3(x1, y1, z1);
            }
            ulonglong2 xy, zw;
            xy.x = pack2(2.f * x0, 2.f * x1);
            xy.y = pack2(2.f * y0, 2.f * y1);
            zw.x = pack2(2.f * z0, 2.f * z1);
            zw.y = pack2(w0, w1);
            s_xy[p] = xy;
            s_zw[p] = zw;
        }
        __syncthreads();
    }

    int lane = threadIdx.x & 31;
    int wid  = (threadIdx.x >> 5) + blockIdx.y * (blockDim.x >> 5);
    int wtot = (blockDim.x >> 5) * gridDim.y;

    for (int base_it = 0; base_it * wtot < ngroups; base_it++) {
        int g = (base_it & 1) ? ((base_it + 1) * wtot - 1 - wid)
                              : (base_it * wtot + wid);
        if (g >= ngroups) continue;

        int r0 = g * IT;
        // Row registers: (-x_i) duplicated in both halves; sq duplicated.
        u64 nax[IT], nay[IT], naz[IT], aw[IT];
#pragma unroll
        for (int t = 0; t < IT; t++) {
            int i = r0 + t;
            int q = i >> 1, h = i & 1;
            ulonglong2 xy = s_xy[q];
            ulonglong2 zw = s_zw[q];
            float a0, a1, xi2, yi2, zi2, wi;
            unpack2(xy.x, a0, a1); xi2 = h ? a1 : a0;
            unpack2(xy.y, a0, a1); yi2 = h ? a1 : a0;
            unpack2(zw.x, a0, a1); zi2 = h ? a1 : a0;
            unpack2(zw.y, a0, a1); wi  = h ? a1 : a0;
            float nx = -0.5f * xi2, ny = -0.5f * yi2, nz = -0.5f * zi2;  // exact
            nax[t] = pack2(nx, nx); nay[t] = pack2(ny, ny);
            naz[t] = pack2(nz, nz); aw[t]  = pack2(wi, wi);
        }

        unsigned* mp = &g_maskw[((size_t)(s * ngroups + g)) * nch64 * 8];
        int cR = r0 >> 6;  // all 4 rows live in chunk cR (r0 % 64 <= 60)
        int cnt0 = 0, cnt1 = 0, cnt2 = 0, cnt3 = 0;

        // Peeled chunk cR: needs j > i predicates.
        {
            int c = cR;
            ulonglong2 xy = s_xy[(c << 5) + lane];
            ulonglong2 zw = s_zw[(c << 5) + lane];
            int j0 = (c << 6) + (lane << 1);
            unsigned me[IT], mo[IT];
#pragma unroll
            for (int t = 0; t < IT; t++) {
                float d0, d1;
                unpack2(d12_jpair(nax[t], nay[t], naz[t], aw[t],
                                  xy.x, xy.y, zw.x, zw.y), d0, d1);
                int i = r0 + t;
                me[t] = __ballot_sync(0xffffffffu, (d0 < CUT2) && (j0 > i));
                mo[t] = __ballot_sync(0xffffffffu, (d1 < CUT2) && (j0 + 1 > i));
            }
            if (lane == 0) {
                *(uint4*)&mp[c * 8]     = make_uint4(me[0], mo[0], me[1], mo[1]);
                *(uint4*)&mp[c * 8 + 4] = make_uint4(me[2], mo[2], me[3], mo[3]);
            }
            cnt0 += __popc(me[0]) + __popc(mo[0]);
            cnt1 += __popc(me[1]) + __popc(mo[1]);
            cnt2 += __popc(me[2]) + __popc(mo[2]);
            cnt3 += __popc(me[3]) + __popc(mo[3]);
        }

        // Clean chunks: j > i guaranteed; sentinel pairs kill j >= nat.
        for (int c = cR + 1; c < nch64; c++) {
            ulonglong2 xy = s_xy[(c << 5) + lane];
            ulonglong2 zw = s_zw[(c << 5) + lane];
            unsigned me[IT], mo[IT];
#pragma unroll
            for (int t = 0; t < IT; t++) {
                float d0, d1;
                unpack2(d12_jpair(nax[t], nay[t], naz[t], aw[t],
                                  xy.x, xy.y, zw.x, zw.y), d0, d1);
                me[t] = __ballot_sync(0xffffffffu, d0 < CUT2);
                mo[t] = __ballot_sync(0xffffffffu, d1 < CUT2);
            }
            if (lane == 0) {
                *(uint4*)&mp[c * 8]     = make_uint4(me[0], mo[0], me[1], mo[1]);
                *(uint4*)&mp[c * 8 + 4] = make_uint4(me[2], mo[2], me[3], mo[3]);
            }
            cnt0 += __popc(me[0]) + __popc(mo[0]);
            cnt1 += __popc(me[1]) + __popc(mo[1]);
            cnt2 += __popc(me[2]) + __popc(mo[2]);
            cnt3 += __popc(me[3]) + __popc(mo[3]);
        }

        if (lane == 0)
            g_counts4[s * ngroups + g] = make_int4(cnt0, cnt1, cnt2, cnt3);
    }
}

// K2: per-system exclusive scan over per-row counts (coalesced int loads).
__global__ void scan_sys_kernel(int nat, int ngroups) {
    __shared__ int wsum[32];
    int s = blockIdx.x;
    int tid = threadIdx.x;
    int lane = tid & 31, w = tid >> 5;

    const int* cnts = (const int*)&g_counts4[(size_t)s * ngroups];
    int v = (tid < nat) ? cnts[tid] : 0;

    int x = v;
#pragma unroll
    for (int o = 1; o < 32; o <<= 1) {
        int u = __shfl_up_sync(0xffffffffu, x, o);
        if (lane >= o) x += u;
    }
    if (lane == 31) wsum[w] = x;
    __syncthreads();
    if (w == 0) {
        int y = wsum[lane];
#pragma unroll
        for (int o = 1; o < 32; o <<= 1) {
            int u = __shfl_up_sync(0xffffffffu, y, o);
            if (lane >= o) y += u;
        }
        wsum[lane] = y;
    }
    __syncthreads();
    int incl = x + ((w > 0) ? wsum[w - 1] : 0);
    if (tid < nat) g_offsets[s * nat + tid] = incl - v;
    if (tid == nat - 1) g_systot[s] = incl;
}

// K3: fused output, hit-parallel. Lane c (< nch64) loads its chunk's (e,o)
// word pair, interleaves into a 64-bit j-ascending mask; shfl-scan positions
// hits; lane k handles the k-th hit (binary search + 64-bit fns), recomputes
// d12 bit-exactly from __ldg coords. Pad blocks run concurrently.
// Output float32 layout (maxp = MAX_PAIRS):
//   [0,M): src   [M,2M): dst    (edge_src = concat(src,dst))
//   [2M,3M): dst [3M,4M): src   (edge_dst = concat(dst,src))
//   [4M,5M): d12 [5M,6M): d12   [6M]: npairs
__global__ void output_kernel(const float* __restrict__ coords,
                              float* __restrict__ out, int maxp, int nrows,
                              int nat, int nsys, int nch64, int ngroups,
                              int WB, float padval, int vec_ok) {
    __shared__ int s_sysoff[NSYS_SM];
    int tid = threadIdx.x;
    if (tid < 32) {
        int per = (nsys + 31) >> 5;
        int bbase = tid * per;
        int loc[8];
        int sum = 0;
        for (int u = 0; u < per && u < 8; u++) {
            int idx = bbase + u;
            int t = (idx < nsys) ? g_systot[idx] : 0;
            loc[u] = sum;
            sum += t;
        }
        int x = sum;
#pragma unroll
        for (int o = 1; o < 32; o <<= 1) {
            int uu = __shfl_up_sync(0xffffffffu, x, o);
            if (tid >= o) x += uu;
        }
        int excl = x - sum;
        for (int u = 0; u < per && u < 8; u++) {
            int idx = bbase + u;
            if (idx < nsys && idx < NSYS_SM) s_sysoff[idx] = excl + loc[u];
        }
        if (tid == 31 && nsys < NSYS_SM) s_sysoff[nsys] = x;  // npairs
    }
    __syncthreads();
    int np = s_sysoff[nsys];

    if (blockIdx.x < WB) {
        int row = blockIdx.x * (blockDim.x >> 5) + (tid >> 5);
        if (row >= nrows) return;              // warp-uniform
        int lane = tid & 31;
        int s = row / nat, i = row - s * nat;
        int g = i >> 2, t = i & 3;
        int c0 = i >> 6;                        // sweep wrote chunks >= c0

        unsigned e = 0, o = 0;
        if (lane >= c0 && lane < nch64) {
            const u64* wp = (const u64*)
                &g_maskw[(((size_t)(s * ngroups + g)) * nch64 + lane) * 8 +
                         (t << 1)];
            u64 w2 = *wp;
            e = (unsigned)w2;
            o = (unsigned)(w2 >> 32);
        }
        int cnt = __popc(e) + __popc(o);

        int x = cnt;  // inclusive scan across lanes (chunks)
#pragma unroll
        for (int oo = 1; oo < 32; oo <<= 1) {
            int u = __shfl_up_sync(0xffffffffu, x, oo);
            if (lane >= oo) x += u;
        }
        int mybase = x - cnt;
        int total = __shfl_sync(0xffffffffu, x, 31);
        if (total == 0) return;                 // warp-uniform

        u64 m64 = bexpand(e) | (bexpand(o) << 1);  // j-ascending 64-bit mask
        unsigned mlo = (unsigned)m64, mhi = (unsigned)(m64 >> 32);

        const float* ci = coords + (size_t)row * 3;
        float xi = __ldg(ci), yi = __ldg(ci + 1), zi = __ldg(ci + 2);
        float4 ai = make_float4(xi, yi, zi, sqnorm3(xi, yi, zi));
        float fsrc = (float)row;
        float fsysbase = (float)(s * nat);
        int off = s_sysoff[s] + g_offsets[row];
        int sysbase = s * nat;

        for (int kb = 0; kb < total; kb += 32) {
            int k = kb + lane;
            int c = 0;  // largest lane c with mybase[c] <= k
#pragma unroll
            for (int st = 16; st; st >>= 1) {
                int tt = c + st;
                int bt = __shfl_sync(0xffffffffu, mybase, tt & 31);
                if (tt < 32 && bt <= k) c = tt;
            }
            unsigned clo = __shfl_sync(0xffffffffu, mlo, c);
            unsigned chi = __shfl_sync(0xffffffffu, mhi, c);
            int bc = __shfl_sync(0xffffffffu, mybase, c);
            if (k < total) {
                int r = k - bc;
                int pl = __popc(clo);
                int bit = (r < pl) ? __fns(clo, 0, r + 1)
                                   : 32 + __fns(chi, 0, r - pl + 1);
                int j = (c << 6) + bit;
                const float* cj = coords + (size_t)(sysbase + j) * 3;
                float xj = __ldg(cj), yj = __ldg(cj + 1), zj = __ldg(cj + 2);
                float4 aj = make_float4(xj, yj, zj, sqnorm3(xj, yj, zj));
                float d = d12_of(ai, aj);
                int pos = off + k;
                if (pos < maxp) {
                    float fdst = fsysbase + (float)j;
                    out[pos]            = fsrc;
                    out[maxp + pos]     = fdst;
                    out[2 * maxp + pos] = fdst;
                    out[3 * maxp + pos] = fsrc;
                    out[4 * maxp + pos] = d;
                    out[5 * maxp + pos] = d;
                }
            }
        }
    } else {
        int pb = blockIdx.x - WB;
        if (pb == 0 && tid == 0) out[6 * maxp] = (float)np;
        int k0 = (pb * blockDim.x + tid) * 4;
        if (k0 >= maxp) return;
        if (k0 >= np && k0 + 3 < maxp && vec_ok) {
            float4 pv = make_float4(padval, padval, padval, padval);
            float4 cv = make_float4(CUT2, CUT2, CUT2, CUT2);
            *(float4*)(out + k0)            = pv;
            *(float4*)(out + maxp + k0)     = pv;
            *(float4*)(out + 2 * maxp + k0) = pv;
            *(float4*)(out + 3 * maxp + k0) = pv;
            *(float4*)(out + 4 * maxp + k0) = cv;
            *(float4*)(out + 5 * maxp + k0) = cv;
        } else {
#pragma unroll
            for (int u = 0; u < 4; u++) {
                int k = k0 + u;
                if (k < maxp && k >= np) {
                    out[k]            = padval;
                    out[maxp + k]     = padval;
                    out[2 * maxp + k] = padval;
                    out[3 * maxp + k] = padval;
                    out[4 * maxp + k] = CUT2;
                    out[5 * maxp + k] = CUT2;
                }
            }
        }
    }
}

extern "C" void kernel_launch(void* const* d_in, const int* in_sizes, int n_in,
                              void* d_out, int out_size) {
    const float* coords = (const float*)d_in[0];
    int n    = in_sizes[1];          // total atoms
    int nsys = in_sizes[2];          // systems
    int nat  = n / nsys;
    int maxp = (out_size - 1) / 6;   // MAX_PAIRS
    float* out = (float*)d_out;

    int nch64 = (nat + 63) >> 6;          // 64-wide j-chunks per row (<= 16)
    int ngroups = (nat + IT - 1) / IT;
    size_t smem_sweep = (size_t)2 * nch64 * 32 * sizeof(ulonglong2);
    int vec_ok = ((maxp & 3) == 0) ? 1 : 0;

    int WB = (n + 7) / 8;                          // write blocks (8 warps ea)
    int PB = (maxp + 256 * 4 - 1) / (256 * 4);     // pad blocks

    sweep_kernel<<<dim3(nsys, 16), 256, smem_sweep>>>(coords, nat, nch64,
                                                      ngroups);
    scan_sys_kernel<<<nsys, 1024>>>(nat, ngroups);
    output_kernel<<<WB + PB, 256>>>(coords, out, maxp, n, nat, nsys, nch64,
                                    ngroups, WB, (float)n, vec_ok);
}

// round 11
// speedup vs baseline: 1.0175x; 1.0175x over previous
#include <cuda_runtime.h>

#define CUT2 25.0f
#define NROWS_CAP 65536
#define NGRP_CAP  (NROWS_CAP / 4)
#define MAXCH 32        // max 32-wide j-chunks per row (nat <= 1024)
#define NSYS_CAP 2048
#define NSYS_SM 257

// Scratch (static __device__, allocation-free).
// Mask layout (same as R9): uint4 per (4-row group, chunk): component t is
// the 32-bit j-mask of row 4g+t over j in [32c, 32c+32).
__device__ uint4 g_mask[(size_t)NGRP_CAP * MAXCH];   // 8 MB
__device__ int   g_cnt[NROWS_CAP];       // per-row hit counts
__device__ int   g_offsets[NROWS_CAP];   // within-system exclusive prefix
__device__ int   g_systot[NSYS_CAP];     // per-system totals

// ---- bit-exact reference arithmetic (DO NOT CHANGE) ----
__device__ __forceinline__ float sqnorm3(float x, float y, float z) {
    return __fadd_rn(__fadd_rn(__fmul_rn(x, x), __fmul_rn(y, y)), __fmul_rn(z, z));
}
// gram dot via GEMM-style FMA chain: c = rn(x*x'); c = fma(y,y',c); c = fma(z,z',c)
__device__ __forceinline__ float dot3(float4 a, float4 b) {
    return __fmaf_rn(a.z, b.z, __fmaf_rn(a.y, b.y, __fmul_rn(a.x, b.x)));
}
__device__ __forceinline__ float d12_of(float4 ai, float4 aj) {
    return __fsub_rn(__fadd_rn(ai.w, aj.w), __fmul_rn(2.0f, dot3(ai, aj)));
}
// --------------------------------------------------------

extern __shared__ float4 s_at[];  // nch*32 entries: (2x, 2y, 2z, sq); sentinels

// K1: row-per-lane mask sweep. Lane l owns row R + l; the warp walks j-chunks;
// s_at[j] loads are warp-broadcast (conflict-free). Each lane accumulates its
// row's 32-bit mask in a register: FSETP + predicated OR per pair — no
// ballots, no popc-ranking. The negated/halved row regs make the FMA chain
// produce -2*dot exactly, so d = rn(rn(wi+wj) - 2*dot): bit-identical to the
// reference d12 (power-of-two scaling and negation commute with rn).
__global__ void sweep_kernel(const float* __restrict__ coords, int nat,
                             int nch, int ngroups) {
    int s = blockIdx.x;
    {
        const float* base = coords + (size_t)s * nat * 3;
        int P = nch * 32;
        for (int t = threadIdx.x; t < P; t += blockDim.x) {
            if (t < nat) {
                float x = base[3 * t + 0];
                float y = base[3 * t + 1];
                float z = base[3 * t + 2];
                s_at[t] = make_float4(2.0f * x, 2.0f * y, 2.0f * z,
                                      sqnorm3(x, y, z));
            } else {
                s_at[t] = make_float4(0.f, 0.f, 0.f, 1e30f);  // never a hit
            }
        }
        __syncthreads();
    }

    int lane = threadIdx.x & 31;
    int wj   = (threadIdx.x >> 5) + blockIdx.y * (blockDim.x >> 5);
    int W    = (blockDim.x >> 5) * gridDim.y;
    int nblk = nch;   // 32-row blocks per system == j-chunks per row

    // Zigzag row-block assignment: pairs (b, nblk-1-b) -> constant cost.
    for (int base_it = 0; base_it * W < nblk; base_it++) {
        int blk = (base_it & 1) ? ((base_it + 1) * W - 1 - wj)
                                : (base_it * W + wj);
        if (blk >= nblk) continue;

        int R = blk << 5;
        int i = R + lane;                  // this lane's row (may be sentinel)
        float4 v = s_at[i];                // i < nch*32 always
        float nx = -0.5f * v.x, ny = -0.5f * v.y, nz = -0.5f * v.z;  // exact
        float wi = v.w;

        int g4 = i >> 2;
        bool g4ok = (g4 < ngroups);
        // word index of (group g4, chunk c, row-slot i&3) = (g4*nch + c)*4 + t
        unsigned* mp = ((unsigned*)g_mask) +
                       (((size_t)s * ngroups + g4) * nch) * 4 + (i & 3);
        int cnt = 0;

        // Diagonal chunk (c == blk): keep only bits j_local > lane.
        {
            const float4* jp = s_at + R;
            unsigned m = 0;
#pragma unroll
            for (int k = 0; k < 32; k++) {
                float4 aj = jp[k];
                float t = __fmul_rn(nx, aj.x);
                t = __fmaf_rn(ny, aj.y, t);
                t = __fmaf_rn(nz, aj.z, t);
                float w = __fadd_rn(wi, aj.w);
                float d = __fadd_rn(w, t);
                if (d < CUT2) m |= (1u << k);
            }
            m &= (0xFFFFFFFEu << lane);
            if (g4ok) mp[(size_t)blk << 2] = m;
            cnt += __popc(m);
        }

        // Chunks above the diagonal: all bits valid; sentinels kill j >= nat.
        for (int c = blk + 1; c < nch; c++) {
            const float4* jp = s_at + (c << 5);
            unsigned m = 0;
#pragma unroll
            for (int k = 0; k < 32; k++) {
                float4 aj = jp[k];
                float t = __fmul_rn(nx, aj.x);
                t = __fmaf_rn(ny, aj.y, t);
                t = __fmaf_rn(nz, aj.z, t);
                float w = __fadd_rn(wi, aj.w);
                float d = __fadd_rn(w, t);
                if (d < CUT2) m |= (1u << k);
            }
            if (g4ok) mp[(size_t)c << 2] = m;
            cnt += __popc(m);
        }

        if (i < nat) g_cnt[s * nat + i] = cnt;   // coalesced
    }
}

// K2: per-system exclusive scan over per-row counts (coalesced int loads).
__global__ void scan_sys_kernel(int nat) {
    __shared__ int wsum[32];
    int s = blockIdx.x;
    int tid = threadIdx.x;
    int lane = tid & 31, w = tid >> 5;

    int v = (tid < nat) ? g_cnt[s * nat + tid] : 0;

    int x = v;
#pragma unroll
    for (int o = 1; o < 32; o <<= 1) {
        int u = __shfl_up_sync(0xffffffffu, x, o);
        if (lane >= o) x += u;
    }
    if (lane == 31) wsum[w] = x;
    __syncthreads();
    if (w == 0) {
        int y = wsum[lane];
#pragma unroll
        for (int o = 1; o < 32; o <<= 1) {
            int u = __shfl_up_sync(0xffffffffu, y, o);
            if (lane >= o) y += u;
        }
        wsum[lane] = y;
    }
    __syncthreads();
    int incl = x + ((w > 0) ? wsum[w - 1] : 0);
    if (tid < nat) g_offsets[s * nat + tid] = incl - v;
    if (tid == nat - 1) g_systot[s] = incl;
}

// K3: fused output (R9-proven), hit-parallel. One warp per row; lane c loads
// chunk c's mask; shfl-scan positions hits; lane k handles the k-th hit of
// the row (binary search + __fns), recomputing d12 bit-exactly from __ldg
// coords. Stores are coalesced. Pad blocks run concurrently.
// Output float32 layout (maxp = MAX_PAIRS):
//   [0,M): src   [M,2M): dst    (edge_src = concat(src,dst))
//   [2M,3M): dst [3M,4M): src   (edge_dst = concat(dst,src))
//   [4M,5M): d12 [5M,6M): d12   [6M]: npairs
__global__ void output_kernel(const float* __restrict__ coords,
                              float* __restrict__ out, int maxp, int nrows,
                              int nat, int nsys, int nch, int ngroups,
                              int WB, float padval, int vec_ok) {
    __shared__ int s_sysoff[NSYS_SM];
    int tid = threadIdx.x;
    if (tid < 32) {
        int per = (nsys + 31) >> 5;
        int bbase = tid * per;
        int loc[8];
        int sum = 0;
        for (int u = 0; u < per && u < 8; u++) {
            int idx = bbase + u;
            int t = (idx < nsys) ? g_systot[idx] : 0;
            loc[u] = sum;
            sum += t;
        }
        int x = sum;
#pragma unroll
        for (int o = 1; o < 32; o <<= 1) {
            int uu = __shfl_up_sync(0xffffffffu, x, o);
            if (tid >= o) x += uu;
        }
        int excl = x - sum;
        for (int u = 0; u < per && u < 8; u++) {
            int idx = bbase + u;
            if (idx < nsys && idx < NSYS_SM) s_sysoff[idx] = excl + loc[u];
        }
        if (tid == 31 && nsys < NSYS_SM) s_sysoff[nsys] = x;  // npairs
    }
    __syncthreads();
    int np = s_sysoff[nsys];

    if (blockIdx.x < WB) {
        int row = blockIdx.x * (blockDim.x >> 5) + (tid >> 5);
        if (row >= nrows) return;              // warp-uniform
        int lane = tid & 31;
        int s = row / nat, i = row - s * nat;
        int g = i >> 2, t = i & 3;
        int c0 = ((g << 2) + 1) >> 5;

        unsigned m = 0;
        if (lane >= c0 && lane < nch)
            m = ((const unsigned*)&g_mask[((size_t)s * ngroups + g) * nch])
                 [(lane << 2) + t];
        int cnt = __popc(m);

        int x = cnt;  // inclusive scan across lanes (chunks)
#pragma unroll
        for (int o = 1; o < 32; o <<= 1) {
            int u = __shfl_up_sync(0xffffffffu, x, o);
            if (lane >= o) x += u;
        }
        int mybase = x - cnt;
        int total = __shfl_sync(0xffffffffu, x, 31);
        if (total == 0) return;                 // warp-uniform

        const float* ci = coords + (size_t)row * 3;
        float xi = __ldg(ci), yi = __ldg(ci + 1), zi = __ldg(ci + 2);
        float4 ai = make_float4(xi, yi, zi, sqnorm3(xi, yi, zi));
        float fsrc = (float)row;
        float fsysbase = (float)(s * nat);
        int off = s_sysoff[s] + g_offsets[row];
        int sysbase = s * nat;

        for (int kb = 0; kb < total; kb += 32) {
            int k = kb + lane;
            int c = 0;  // largest lane c with mybase[c] <= k
#pragma unroll
            for (int st = 16; st; st >>= 1) {
                int tt = c + st;
                int bt = __shfl_sync(0xffffffffu, mybase, tt & 31);
                if (tt < 32 && bt <= k) c = tt;
            }
            unsigned mc = __shfl_sync(0xffffffffu, m, c);
            int bc = __shfl_sync(0xffffffffu, mybase, c);
            if (k < total) {
                int r = k - bc;
                int bit = __fns(mc, 0, r + 1);
                int j = (c << 5) + bit;
                const float* cj = coords + (size_t)(sysbase + j) * 3;
                float xj = __ldg(cj), yj = __ldg(cj + 1), zj = __ldg(cj + 2);
                float4 aj = make_float4(xj, yj, zj, sqnorm3(xj, yj, zj));
                float d = d12_of(ai, aj);
                int pos = off + k;
                if (pos < maxp) {
                    float fdst = fsysbase + (float)j;
                    out[pos]            = fsrc;
                    out[maxp + pos]     = fdst;
                    out[2 * maxp + pos] = fdst;
                    out[3 * maxp + pos] = fsrc;
                    out[4 * maxp + pos] = d;
                    out[5 * maxp + pos] = d;
                }
            }
        }
    } else {
        int pb = blockIdx.x - WB;
        if (pb == 0 && tid == 0) out[6 * maxp] = (float)np;
        int k0 = (pb * blockDim.x + tid) * 4;
        if (k0 >= maxp) return;
        if (k0 >= np && k0 + 3 < maxp && vec_ok) {
            float4 pv = make_float4(padval, padval, padval, padval);
            float4 cv = make_float4(CUT2, CUT2, CUT2, CUT2);
            *(float4*)(out + k0)            = pv;
            *(float4*)(out + maxp + k0)     = pv;
            *(float4*)(out + 2 * maxp + k0) = pv;
            *(float4*)(out + 3 * maxp + k0) = pv;
            *(float4*)(out + 4 * maxp + k0) = cv;
            *(float4*)(out + 5 * maxp + k0) = cv;
        } else {
#pragma unroll
            for (int u = 0; u < 4; u++) {
                int k = k0 + u;
                if (k < maxp && k >= np) {
                    out[k]            = padval;
                    out[maxp + k]     = padval;
                    out[2 * maxp + k] = padval;
                    out[3 * maxp + k] = padval;
                    out[4 * maxp + k] = CUT2;
                    out[5 * maxp + k] = CUT2;
                }
            }
        }
    }
}

extern "C" void kernel_launch(void* const* d_in, const int* in_sizes, int n_in,
                              void* d_out, int out_size) {
    const float* coords = (const float*)d_in[0];
    int n    = in_sizes[1];          // total atoms
    int nsys = in_sizes[2];          // systems
    int nat  = n / nsys;
    int maxp = (out_size - 1) / 6;   // MAX_PAIRS
    float* out = (float*)d_out;

    int nch = (nat + 31) >> 5;            // 32-wide j-chunks per row (<= 32)
    int ngroups = (nat + 3) >> 2;         // 4-row mask groups per system
    size_t smem_sweep = (size_t)nch * 32 * sizeof(float4);
    int vec_ok = ((maxp & 3) == 0) ? 1 : 0;

    int WB = (n + 7) / 8;                          // write blocks (8 warps ea)
    int PB = (maxp + 256 * 4 - 1) / (256 * 4);     // pad blocks

    sweep_kernel<<<dim3(nsys, 2), 256, smem_sweep>>>(coords, nat, nch, ngroups);
    scan_sys_kernel<<<nsys, 1024>>>(nat);
    output_kernel<<<WB + PB, 256>>>(coords, out, maxp, n, nat, nsys, nch,
                                    ngroups, WB, (float)n, vec_ok);
}

// round 12
// speedup vs baseline: 1.1821x; 1.1618x over previous
#include <cuda_runtime.h>

#define CUT2 25.0f
#define QS 4            // j-quarter split: 4 warps share one row-block
#define NROWS_CAP 65536
#define NGRP_CAP  (NROWS_CAP / 4)
#define MAXCH 32        // max 32-wide j-chunks per row (nat <= 1024)
#define NSYS_CAP 2048
#define NSYS_SM 257

// Scratch (static __device__, allocation-free).
// Mask layout (R9-proven): uint4 per (4-row group, chunk): component t is
// the 32-bit j-mask of row 4g+t over j in [32c, 32c+32).
__device__ uint4 g_mask[(size_t)NGRP_CAP * MAXCH];   // 8 MB
__device__ int   g_cntp[(size_t)NROWS_CAP * QS];     // per-(row, quarter) counts
__device__ int   g_offsets[NROWS_CAP];   // within-system exclusive prefix
__device__ int   g_systot[NSYS_CAP];     // per-system totals

// ---- bit-exact reference arithmetic (DO NOT CHANGE) ----
__device__ __forceinline__ float sqnorm3(float x, float y, float z) {
    return __fadd_rn(__fadd_rn(__fmul_rn(x, x), __fmul_rn(y, y)), __fmul_rn(z, z));
}
// gram dot via GEMM-style FMA chain: c = rn(x*x'); c = fma(y,y',c); c = fma(z,z',c)
__device__ __forceinline__ float dot3(float4 a, float4 b) {
    return __fmaf_rn(a.z, b.z, __fmaf_rn(a.y, b.y, __fmul_rn(a.x, b.x)));
}
__device__ __forceinline__ float d12_of(float4 ai, float4 aj) {
    return __fsub_rn(__fadd_rn(ai.w, aj.w), __fmul_rn(2.0f, dot3(ai, aj)));
}
// --------------------------------------------------------

extern __shared__ float4 s_at[];  // nch*32 entries: (2x, 2y, 2z, sq); sentinels

// K1: row-per-lane mask sweep with j-quarter split. Work item (blk, q):
// lane l owns row 32*blk + l; the warp walks chunks c = blk+q, blk+q+QS, ...
// s_at[j] loads are warp-broadcast. Each lane accumulates its row's 32-bit
// mask per chunk in a register (FSETP + predicated OR — no ballots). The
// negated/halved row regs make the FMA chain produce -2*dot exactly, so
// d = rn(rn(wi+wj) - 2*dot): bit-identical to the reference d12.
__global__ void sweep_kernel(const float* __restrict__ coords, int nat,
                             int nch, int ngroups) {
    int s = blockIdx.x;
    {
        const float* base = coords + (size_t)s * nat * 3;
        int P = nch * 32;
        for (int t = threadIdx.x; t < P; t += blockDim.x) {
            if (t < nat) {
                float x = base[3 * t + 0];
                float y = base[3 * t + 1];
                float z = base[3 * t + 2];
                s_at[t] = make_float4(2.0f * x, 2.0f * y, 2.0f * z,
                                      sqnorm3(x, y, z));
            } else {
                s_at[t] = make_float4(0.f, 0.f, 0.f, 1e30f);  // never a hit
            }
        }
        __syncthreads();
    }

    int lane = threadIdx.x & 31;
    int wj   = (threadIdx.x >> 5) + blockIdx.y * (blockDim.x >> 5);
    int W    = (blockDim.x >> 5) * gridDim.y;
    int NI   = nch * QS;                 // flattened items (blk, q)

    // Zigzag item assignment: costs decrease with item index, so pairing
    // (it, NI-1-it) gives each warp near-constant total work.
    for (int base_it = 0; base_it * W < NI; base_it++) {
        int it = (base_it & 1) ? ((base_it + 1) * W - 1 - wj)
                               : (base_it * W + wj);
        if (it >= NI) continue;
        int blk = it >> 2, q = it & 3;

        int R = blk << 5;
        int i = R + lane;                  // this lane's row (may be sentinel)
        float4 v = s_at[i];
        float nx = -0.5f * v.x, ny = -0.5f * v.y, nz = -0.5f * v.z;  // exact
        float wi = v.w;

        int g4 = i >> 2;
        bool g4ok = (g4 < ngroups);
        unsigned* mp = ((unsigned*)g_mask) +
                       (((size_t)s * ngroups + g4) * nch) * 4 + (i & 3);
        int cnt = 0;
        int c = blk + q;

        // Diagonal chunk (only item q == 0): keep bits j_local > lane.
        if (q == 0 && c < nch) {
            const float4* jp = s_at + (c << 5);
            unsigned m = 0;
#pragma unroll
            for (int k = 0; k < 32; k++) {
                float4 aj = jp[k];
                float t = __fmul_rn(nx, aj.x);
                t = __fmaf_rn(ny, aj.y, t);
                t = __fmaf_rn(nz, aj.z, t);
                float w = __fadd_rn(wi, aj.w);
                float d = __fadd_rn(w, t);
                if (d < CUT2) m |= (1u << k);
            }
            m &= (0xFFFFFFFEu << lane);
            if (g4ok) mp[(size_t)c << 2] = m;
            cnt += __popc(m);
            c += QS;
        }

        // Clean chunks: all bits valid; sentinels kill j >= nat.
        for (; c < nch; c += QS) {
            const float4* jp = s_at + (c << 5);
            unsigned m = 0;
#pragma unroll
            for (int k = 0; k < 32; k++) {
                float4 aj = jp[k];
                float t = __fmul_rn(nx, aj.x);
                t = __fmaf_rn(ny, aj.y, t);
                t = __fmaf_rn(nz, aj.z, t);
                float w = __fadd_rn(wi, aj.w);
                float d = __fadd_rn(w, t);
                if (d < CUT2) m |= (1u << k);
            }
            if (g4ok) mp[(size_t)c << 2] = m;
            cnt += __popc(m);
        }

        if (i < nat) g_cntp[((size_t)s * nat + i) * QS + q] = cnt;
    }
}

// K2: per-system exclusive scan; row count = sum of QS=4 partials (int4 load).
__global__ void scan_sys_kernel(int nat) {
    __shared__ int wsum[32];
    int s = blockIdx.x;
    int tid = threadIdx.x;
    int lane = tid & 31, w = tid >> 5;

    int v = 0;
    if (tid < nat) {
        int4 p = *(const int4*)&g_cntp[((size_t)s * nat + tid) * QS];
        v = p.x + p.y + p.z + p.w;
    }

    int x = v;
#pragma unroll
    for (int o = 1; o < 32; o <<= 1) {
        int u = __shfl_up_sync(0xffffffffu, x, o);
        if (lane >= o) x += u;
    }
    if (lane == 31) wsum[w] = x;
    __syncthreads();
    if (w == 0) {
        int y = wsum[lane];
#pragma unroll
        for (int o = 1; o < 32; o <<= 1) {
            int u = __shfl_up_sync(0xffffffffu, y, o);
            if (lane >= o) y += u;
        }
        wsum[lane] = y;
    }
    __syncthreads();
    int incl = x + ((w > 0) ? wsum[w - 1] : 0);
    if (tid < nat) g_offsets[s * nat + tid] = incl - v;
    if (tid == nat - 1) g_systot[s] = incl;
}

// K3: fused output (R9-proven), hit-parallel. One warp per row; lane c loads
// chunk c's mask; shfl-scan positions hits; lane k handles the k-th hit
// (binary search + __fns), recomputing d12 bit-exactly from __ldg coords.
// Stores coalesced. Pad blocks run concurrently.
// Output float32 layout (maxp = MAX_PAIRS):
//   [0,M): src   [M,2M): dst    (edge_src = concat(src,dst))
//   [2M,3M): dst [3M,4M): src   (edge_dst = concat(dst,src))
//   [4M,5M): d12 [5M,6M): d12   [6M]: npairs
__global__ void output_kernel(const float* __restrict__ coords,
                              float* __restrict__ out, int maxp, int nrows,
                              int nat, int nsys, int nch, int ngroups,
                              int WB, float padval, int vec_ok) {
    __shared__ int s_sysoff[NSYS_SM];
    int tid = threadIdx.x;
    if (tid < 32) {
        int per = (nsys + 31) >> 5;
        int bbase = tid * per;
        int loc[8];
        int sum = 0;
        for (int u = 0; u < per && u < 8; u++) {
            int idx = bbase + u;
            int t = (idx < nsys) ? g_systot[idx] : 0;
            loc[u] = sum;
            sum += t;
        }
        int x = sum;
#pragma unroll
        for (int o = 1; o < 32; o <<= 1) {
            int uu = __shfl_up_sync(0xffffffffu, x, o);
            if (tid >= o) x += uu;
        }
        int excl = x - sum;
        for (int u = 0; u < per && u < 8; u++) {
            int idx = bbase + u;
            if (idx < nsys && idx < NSYS_SM) s_sysoff[idx] = excl + loc[u];
        }
        if (tid == 31 && nsys < NSYS_SM) s_sysoff[nsys] = x;  // npairs
    }
    __syncthreads();
    int np = s_sysoff[nsys];

    if (blockIdx.x < WB) {
        int row = blockIdx.x * (blockDim.x >> 5) + (tid >> 5);
        if (row >= nrows) return;              // warp-uniform
        int lane = tid & 31;
        int s = row / nat, i = row - s * nat;
        int g = i >> 2, t = i & 3;
        int c0 = i >> 5;                        // sweep wrote chunks >= i>>5

        unsigned m = 0;
        if (lane >= c0 && lane < nch)
            m = ((const unsigned*)&g_mask[((size_t)s * ngroups + g) * nch])
                 [(lane << 2) + t];
        int cnt = __popc(m);

        int x = cnt;  // inclusive scan across lanes (chunks)
#pragma unroll
        for (int o = 1; o < 32; o <<= 1) {
            int u = __shfl_up_sync(0xffffffffu, x, o);
            if (lane >= o) x += u;
        }
        int mybase = x - cnt;
        int total = __shfl_sync(0xffffffffu, x, 31);
        if (total == 0) return;                 // warp-uniform

        const float* ci = coords + (size_t)row * 3;
        float xi = __ldg(ci), yi = __ldg(ci + 1), zi = __ldg(ci + 2);
        float4 ai = make_float4(xi, yi, zi, sqnorm3(xi, yi, zi));
        float fsrc = (float)row;
        float fsysbase = (float)(s * nat);
        int off = s_sysoff[s] + g_offsets[row];
        int sysbase = s * nat;

        for (int kb = 0; kb < total; kb += 32) {
            int k = kb + lane;
            int c = 0;  // largest lane c with mybase[c] <= k
#pragma unroll
            for (int st = 16; st; st >>= 1) {
                int tt = c + st;
                int bt = __shfl_sync(0xffffffffu, mybase, tt & 31);
                if (tt < 32 && bt <= k) c = tt;
            }
            unsigned mc = __shfl_sync(0xffffffffu, m, c);
            int bc = __shfl_sync(0xffffffffu, mybase, c);
            if (k < total) {
                int r = k - bc;
                int bit = __fns(mc, 0, r + 1);
                int j = (c << 5) + bit;
                const float* cj = coords + (size_t)(sysbase + j) * 3;
                float xj = __ldg(cj), yj = __ldg(cj + 1), zj = __ldg(cj + 2);
                float4 aj = make_float4(xj, yj, zj, sqnorm3(xj, yj, zj));
                float d = d12_of(ai, aj);
                int pos = off + k;
                if (pos < maxp) {
                    float fdst = fsysbase + (float)j;
                    out[pos]            = fsrc;
                    out[maxp + pos]     = fdst;
                    out[2 * maxp + pos] = fdst;
                    out[3 * maxp + pos] = fsrc;
                    out[4 * maxp + pos] = d;
                    out[5 * maxp + pos] = d;
                }
            }
        }
    } else {
        int pb = blockIdx.x - WB;
        if (pb == 0 && tid == 0) out[6 * maxp] = (float)np;
        int k0 = (pb * blockDim.x + tid) * 4;
        if (k0 >= maxp) return;
        if (k0 >= np && k0 + 3 < maxp && vec_ok) {
            float4 pv = make_float4(padval, padval, padval, padval);
            float4 cv = make_float4(CUT2, CUT2, CUT2, CUT2);
            *(float4*)(out + k0)            = pv;
            *(float4*)(out + maxp + k0)     = pv;
            *(float4*)(out + 2 * maxp + k0) = pv;
            *(float4*)(out + 3 * maxp + k0) = pv;
            *(float4*)(out + 4 * maxp + k0) = cv;
            *(float4*)(out + 5 * maxp + k0) = cv;
        } else {
#pragma unroll
            for (int u = 0; u < 4; u++) {
                int k = k0 + u;
                if (k < maxp && k >= np) {
                    out[k]            = padval;
                    out[maxp + k]     = padval;
                    out[2 * maxp + k] = padval;
                    out[3 * maxp + k] = padval;
                    out[4 * maxp + k] = CUT2;
                    out[5 * maxp + k] = CUT2;
                }
            }
        }
    }
}

extern "C" void kernel_launch(void* const* d_in, const int* in_sizes, int n_in,
                              void* d_out, int out_size) {
    const float* coords = (const float*)d_in[0];
    int n    = in_sizes[1];          // total atoms
    int nsys = in_sizes[2];          // systems
    int nat  = n / nsys;
    int maxp = (out_size - 1) / 6;   // MAX_PAIRS
    float* out = (float*)d_out;

    int nch = (nat + 31) >> 5;            // 32-wide j-chunks per row (<= 32)
    int ngroups = (nat + 3) >> 2;         // 4-row mask groups per system
    size_t smem_sweep = (size_t)nch * 32 * sizeof(float4);
    int vec_ok = ((maxp & 3) == 0) ? 1 : 0;

    int WB = (n + 7) / 8;                          // write blocks (8 warps ea)
    int PB = (maxp + 256 * 4 - 1) / (256 * 4);     // pad blocks

    sweep_kernel<<<dim3(nsys, 8), 256, smem_sweep>>>(coords, nat, nch, ngroups);
    scan_sys_kernel<<<nsys, 1024>>>(nat);
    output_kernel<<<WB + PB, 256>>>(coords, out, maxp, n, nat, nsys, nch,
                                    ngroups, WB, (float)n, vec_ok);
}

// round 13
// speedup vs baseline: 1.2421x; 1.0508x over previous
#include <cuda_runtime.h>

#define CUT2 25.0f
#define QS 4            // j-quarter split: 4 warps share one row-block
#define HCAP 128        // per-warp staged-hit capacity (max row degree ~60)
#define NROWS_CAP 65536
#define NGRP_CAP  (NROWS_CAP / 4)
#define MAXCH 32        // max 32-wide j-chunks per row (nat <= 1024)
#define NSYS_CAP 2048
#define NSYS_SM 257

// Scratch (static __device__, allocation-free).
// Mask layout (R9-proven): uint4 per (4-row group, chunk): component t is
// the 32-bit j-mask of row 4g+t over j in [32c, 32c+32).
__device__ uint4 g_mask[(size_t)NGRP_CAP * MAXCH];   // 8 MB
__device__ int   g_cntp[(size_t)NROWS_CAP * QS];     // per-(row, quarter) counts
__device__ int   g_offsets[NROWS_CAP];   // within-system exclusive prefix
__device__ int   g_systot[NSYS_CAP];     // per-system totals

// ---- bit-exact reference arithmetic (DO NOT CHANGE) ----
__device__ __forceinline__ float sqnorm3(float x, float y, float z) {
    return __fadd_rn(__fadd_rn(__fmul_rn(x, x), __fmul_rn(y, y)), __fmul_rn(z, z));
}
// gram dot via GEMM-style FMA chain: c = rn(x*x'); c = fma(y,y',c); c = fma(z,z',c)
__device__ __forceinline__ float dot3(float4 a, float4 b) {
    return __fmaf_rn(a.z, b.z, __fmaf_rn(a.y, b.y, __fmul_rn(a.x, b.x)));
}
__device__ __forceinline__ float d12_of(float4 ai, float4 aj) {
    return __fsub_rn(__fadd_rn(ai.w, aj.w), __fmul_rn(2.0f, dot3(ai, aj)));
}
// --------------------------------------------------------

extern __shared__ float4 s_at[];  // nch*32 entries: (2x, 2y, 2z, sq); sentinels

// K1: row-per-lane mask sweep with j-quarter split. Work item (blk, q):
// lane l owns row 32*blk + l; the warp walks chunks c = blk+q, blk+q+QS, ...
// s_at[j] loads are warp-broadcast. Each lane accumulates its row's 32-bit
// mask per chunk in a register (FSETP + predicated OR — no ballots). The
// negated/halved row regs make the FMA chain produce -2*dot exactly, so
// d = rn(rn(wi+wj) - 2*dot): bit-identical to the reference d12.
__global__ void sweep_kernel(const float* __restrict__ coords, int nat,
                             int nch, int ngroups) {
    int s = blockIdx.x;
    {
        const float* base = coords + (size_t)s * nat * 3;
        int P = nch * 32;
        for (int t = threadIdx.x; t < P; t += blockDim.x) {
            if (t < nat) {
                float x = base[3 * t + 0];
                float y = base[3 * t + 1];
                float z = base[3 * t + 2];
                s_at[t] = make_float4(2.0f * x, 2.0f * y, 2.0f * z,
                                      sqnorm3(x, y, z));
            } else {
                s_at[t] = make_float4(0.f, 0.f, 0.f, 1e30f);  // never a hit
            }
        }
        __syncthreads();
    }

    int lane = threadIdx.x & 31;
    int wj   = (threadIdx.x >> 5) + blockIdx.y * (blockDim.x >> 5);
    int W    = (blockDim.x >> 5) * gridDim.y;
    int NI   = nch * QS;                 // flattened items (blk, q)

    // Zigzag item assignment (generic; at W == NI it's one item per warp).
    for (int base_it = 0; base_it * W < NI; base_it++) {
        int it = (base_it & 1) ? ((base_it + 1) * W - 1 - wj)
                               : (base_it * W + wj);
        if (it >= NI) continue;
        int blk = it >> 2, q = it & 3;

        int R = blk << 5;
        int i = R + lane;                  // this lane's row (may be sentinel)
        float4 v = s_at[i];
        float nx = -0.5f * v.x, ny = -0.5f * v.y, nz = -0.5f * v.z;  // exact
        float wi = v.w;

        int g4 = i >> 2;
        bool g4ok = (g4 < ngroups);
        unsigned* mp = ((unsigned*)g_mask) +
                       (((size_t)s * ngroups + g4) * nch) * 4 + (i & 3);
        int cnt = 0;
        int c = blk + q;

        // Diagonal chunk (only item q == 0): keep bits j_local > lane.
        if (q == 0 && c < nch) {
            const float4* jp = s_at + (c << 5);
            unsigned m = 0;
#pragma unroll
            for (int k = 0; k < 32; k++) {
                float4 aj = jp[k];
                float t = __fmul_rn(nx, aj.x);
                t = __fmaf_rn(ny, aj.y, t);
                t = __fmaf_rn(nz, aj.z, t);
                float w = __fadd_rn(wi, aj.w);
                float d = __fadd_rn(w, t);
                if (d < CUT2) m |= (1u << k);
            }
            m &= (0xFFFFFFFEu << lane);
            if (g4ok) mp[(size_t)c << 2] = m;
            cnt += __popc(m);
            c += QS;
        }

        // Clean chunks: all bits valid; sentinels kill j >= nat.
        for (; c < nch; c += QS) {
            const float4* jp = s_at + (c << 5);
            unsigned m = 0;
#pragma unroll
            for (int k = 0; k < 32; k++) {
                float4 aj = jp[k];
                float t = __fmul_rn(nx, aj.x);
                t = __fmaf_rn(ny, aj.y, t);
                t = __fmaf_rn(nz, aj.z, t);
                float w = __fadd_rn(wi, aj.w);
                float d = __fadd_rn(w, t);
                if (d < CUT2) m |= (1u << k);
            }
            if (g4ok) mp[(size_t)c << 2] = m;
            cnt += __popc(m);
        }

        if (i < nat) g_cntp[((size_t)s * nat + i) * QS + q] = cnt;
    }
}

// K2: per-system exclusive scan; row count = sum of QS=4 partials (int4 load).
__global__ void scan_sys_kernel(int nat) {
    __shared__ int wsum[32];
    int s = blockIdx.x;
    int tid = threadIdx.x;
    int lane = tid & 31, w = tid >> 5;

    int v = 0;
    if (tid < nat) {
        int4 p = *(const int4*)&g_cntp[((size_t)s * nat + tid) * QS];
        v = p.x + p.y + p.z + p.w;
    }

    int x = v;
#pragma unroll
    for (int o = 1; o < 32; o <<= 1) {
        int u = __shfl_up_sync(0xffffffffu, x, o);
        if (lane >= o) x += u;
    }
    if (lane == 31) wsum[w] = x;
    __syncthreads();
    if (w == 0) {
        int y = wsum[lane];
#pragma unroll
        for (int o = 1; o < 32; o <<= 1) {
            int u = __shfl_up_sync(0xffffffffu, y, o);
            if (lane >= o) y += u;
        }
        wsum[lane] = y;
    }
    __syncthreads();
    int incl = x + ((w > 0) ? wsum[w - 1] : 0);
    if (tid < nat) g_offsets[s * nat + tid] = incl - v;
    if (tid == nat - 1) g_systot[s] = incl;
}

// K3: fused output, hit-parallel via per-warp smem staging. One warp per row;
// lane c loads chunk c's mask; shfl-scan of popcounts gives per-chunk bases;
// each lane serially STS's its own chunk's hit j-indices at their final
// positions; after __syncwarp, lane k handles the k-th hit (LDS, no shfl
// binary search), recomputing d12 bit-exactly from __ldg coords. Stores
// coalesced. Pad blocks run concurrently.
// Output float32 layout (maxp = MAX_PAIRS):
//   [0,M): src   [M,2M): dst    (edge_src = concat(src,dst))
//   [2M,3M): dst [3M,4M): src   (edge_dst = concat(dst,src))
//   [4M,5M): d12 [5M,6M): d12   [6M]: npairs
__global__ void output_kernel(const float* __restrict__ coords,
                              float* __restrict__ out, int maxp, int nrows,
                              int nat, int nsys, int nch, int ngroups,
                              int WB, float padval, int vec_ok) {
    __shared__ int s_sysoff[NSYS_SM];
    __shared__ int s_hits[8][HCAP];
    int tid = threadIdx.x;
    if (tid < 32) {
        int per = (nsys + 31) >> 5;
        int bbase = tid * per;
        int loc[8];
        int sum = 0;
        for (int u = 0; u < per && u < 8; u++) {
            int idx = bbase + u;
            int t = (idx < nsys) ? g_systot[idx] : 0;
            loc[u] = sum;
            sum += t;
        }
        int x = sum;
#pragma unroll
        for (int o = 1; o < 32; o <<= 1) {
            int uu = __shfl_up_sync(0xffffffffu, x, o);
            if (tid >= o) x += uu;
        }
        int excl = x - sum;
        for (int u = 0; u < per && u < 8; u++) {
            int idx = bbase + u;
            if (idx < nsys && idx < NSYS_SM) s_sysoff[idx] = excl + loc[u];
        }
        if (tid == 31 && nsys < NSYS_SM) s_sysoff[nsys] = x;  // npairs
    }
    __syncthreads();
    int np = s_sysoff[nsys];

    if (blockIdx.x < WB) {
        int row = blockIdx.x * (blockDim.x >> 5) + (tid >> 5);
        if (row >= nrows) return;              // warp-uniform
        int lane = tid & 31;
        int w = tid >> 5;
        int s = row / nat, i = row - s * nat;
        int g = i >> 2, t = i & 3;
        int c0 = i >> 5;                        // sweep wrote chunks >= i>>5

        unsigned m = 0;
        if (lane >= c0 && lane < nch)
            m = ((const unsigned*)&g_mask[((size_t)s * ngroups + g) * nch])
                 [(lane << 2) + t];
        int cnt = __popc(m);

        int x = cnt;  // inclusive scan across lanes (chunks)
#pragma unroll
        for (int o = 1; o < 32; o <<= 1) {
            int u = __shfl_up_sync(0xffffffffu, x, o);
            if (lane >= o) x += u;
        }
        int mybase = x - cnt;
        int total = __shfl_sync(0xffffffffu, x, 31);
        if (total == 0) return;                 // warp-uniform

        // Stage this chunk's hit j-indices at their final in-row positions.
        {
            unsigned mm = m;
            int r = mybase;
            int jb = lane << 5;
            while (mm) {
                int b = __ffs(mm) - 1;
                mm &= mm - 1;
                if (r < HCAP) s_hits[w][r] = jb + b;
                r++;
            }
        }
        __syncwarp();

        const float* ci = coords + (size_t)row * 3;
        float xi = __ldg(ci), yi = __ldg(ci + 1), zi = __ldg(ci + 2);
        float4 ai = make_float4(xi, yi, zi, sqnorm3(xi, yi, zi));
        float fsrc = (float)row;
        float fsysbase = (float)(s * nat);
        int off = s_sysoff[s] + g_offsets[row];
        int sysbase = s * nat;

        for (int kb = 0; kb < total; kb += 32) {
            int k = kb + lane;
            if (k < total && k < HCAP) {
                int j = s_hits[w][k];
                const float* cj = coords + (size_t)(sysbase + j) * 3;
                float xj = __ldg(cj), yj = __ldg(cj + 1), zj = __ldg(cj + 2);
                float4 aj = make_float4(xj, yj, zj, sqnorm3(xj, yj, zj));
                float d = d12_of(ai, aj);
                int pos = off + k;
                if (pos < maxp) {
                    float fdst = fsysbase + (float)j;
                    out[pos]            = fsrc;
                    out[maxp + pos]     = fdst;
                    out[2 * maxp + pos] = fdst;
                    out[3 * maxp + pos] = fsrc;
                    out[4 * maxp + pos] = d;
                    out[5 * maxp + pos] = d;
                }
            }
        }
    } else {
        int pb = blockIdx.x - WB;
        if (pb == 0 && tid == 0) out[6 * maxp] = (float)np;
        int k0 = (pb * blockDim.x + tid) * 4;
        if (k0 >= maxp) return;
        if (k0 >= np && k0 + 3 < maxp && vec_ok) {
            float4 pv = make_float4(padval, padval, padval, padval);
            float4 cv = make_float4(CUT2, CUT2, CUT2, CUT2);
            *(float4*)(out + k0)            = pv;
            *(float4*)(out + maxp + k0)     = pv;
            *(float4*)(out + 2 * maxp + k0) = pv;
            *(float4*)(out + 3 * maxp + k0) = pv;
            *(float4*)(out + 4 * maxp + k0) = cv;
            *(float4*)(out + 5 * maxp + k0) = cv;
        } else {
#pragma unroll
            for (int u = 0; u < 4; u++) {
                int k = k0 + u;
                if (k < maxp && k >= np) {
                    out[k]            = padval;
                    out[maxp + k]     = padval;
                    out[2 * maxp + k] = padval;
                    out[3 * maxp + k] = padval;
                    out[4 * maxp + k] = CUT2;
                    out[5 * maxp + k] = CUT2;
                }
            }
        }
    }
}

extern "C" void kernel_launch(void* const* d_in, const int* in_sizes, int n_in,
                              void* d_out, int out_size) {
    const float* coords = (const float*)d_in[0];
    int n    = in_sizes[1];          // total atoms
    int nsys = in_sizes[2];          // systems
    int nat  = n / nsys;
    int maxp = (out_size - 1) / 6;   // MAX_PAIRS
    float* out = (float*)d_out;

    int nch = (nat + 31) >> 5;            // 32-wide j-chunks per row (<= 32)
    int ngroups = (nat + 3) >> 2;         // 4-row mask groups per system
    size_t smem_sweep = (size_t)nch * 32 * sizeof(float4);
    int vec_ok = ((maxp & 3) == 0) ? 1 : 0;

    int WB = (n + 7) / 8;                          // write blocks (8 warps ea)
    int PB = (maxp + 256 * 4 - 1) / (256 * 4);     // pad blocks

    sweep_kernel<<<dim3(nsys, 16), 256, smem_sweep>>>(coords, nat, nch,
                                                      ngroups);
    scan_sys_kernel<<<nsys, 1024>>>(nat);
    output_kernel<<<WB + PB, 256>>>(coords, out, maxp, n, nat, nsys, nch,
                                    ngroups, WB, (float)n, vec_ok);
}